// round 16
// baseline (speedup 1.0000x reference)
#include <cuda_runtime.h>
#include <cuda_fp16.h>
#include <math.h>
#include <stdint.h>

#define NPTS   (1 << 20)
#define RESG   160
#define TILE   128
#define NTILES (NPTS / TILE)
#define THREADS 512

#define RW2 64   // u32 per row (K=128 halves)
#define RRF 32   // u32 per row (K=64 halves)

// ---- u32 offsets in shared ----
#define U_DW2T 0
#define U_RW2T 8192
#define U_RW1T 16384            // rgb L1 weights, 128n x 32 u32
#define U_HD   20480            // 128 rows x 64 u32
#define U_HR   28672
#define U_RF0  36864            // 128 rows x 32 u32
#define U_RF1  40960
#define F_DB1  45056
#define F_DB2  (F_DB1 + 128)
#define F_RB1  (F_DB2 + 128)
#define F_RB2  (F_RB1 + 128)
#define F_DW3  (F_RB2 + 128)
#define F_RW3  (F_DW3 + 128)    // [3][128]
#define F_DB3  (F_RW3 + 384)
#define F_RB3  (F_DB3 + 1)      // 3
#define F_PD   (F_RB3 + 3)      // [4][128]
#define F_PR   (F_PD + 512)     // [3][4][128]
#define SMEM_U32   (F_PR + 1536)
#define SMEM_BYTES (SMEM_U32 * 4)

#define BARC(id) asm volatile("bar.sync %0, 256;" :: "r"(id) : "memory")

__device__ __forceinline__ int physu(int j, int par) {
    return (((j >> 4) ^ par) << 4) | ((j & 3) << 2) | ((j >> 2) & 3);
}
__device__ __forceinline__ uint32_t packh2(float lo, float hi) {
    __half2 h = __floats2half2_rn(lo, hi);
    return *(uint32_t*)&h;
}
__device__ __forceinline__ void mma16(float c[4], uint32_t a0, uint32_t a1,
                                      uint32_t a2, uint32_t a3,
                                      uint32_t b0, uint32_t b1) {
    asm volatile(
        "mma.sync.aligned.m16n8k16.row.col.f32.f16.f16.f32 "
        "{%0,%1,%2,%3}, {%4,%5,%6,%7}, {%8,%9}, {%0,%1,%2,%3};"
        : "+f"(c[0]), "+f"(c[1]), "+f"(c[2]), "+f"(c[3])
        : "r"(a0), "r"(a1), "r"(a2), "r"(a3), "r"(b0), "r"(b1));
}

// ---- gather stage A: compute weights, issue 6 grid LDG.128 into g[24] ----
__device__ __forceinline__ void gatherA(const float* __restrict__ grid,
                                        float4 xa, int tid,
                                        float g[24], float& w0, float& w1) {
    const int s2 = tid & 3;
    float px = fminf(fmaxf(xa.x, 0.f), 1.f);
    float py = fminf(fmaxf(xa.y, 0.f), 1.f);
    float pz = fminf(fmaxf(xa.z, 0.f), 1.f);
    float fx = px * 159.f, fy = py * 159.f, fz = pz * 159.f;
    float x0f = fminf(floorf(fx), 158.f);
    float y0f = fminf(floorf(fy), 158.f);
    float z0f = fminf(floorf(fz), 158.f);
    float wx = fx - x0f, wy = fy - y0f, wz = fz - z0f;
    int hy = s2 >> 1, hz = s2 & 1;
    int yi = (int)y0f + hy, zi = (int)z0f + hz;
    float wyz = (hy ? wy : 1.f - wy) * (hz ? wz : 1.f - wz);
    w0 = (1.f - wx) * wyz;
    w1 = wx * wyz;
    const float* gp0 = grid + (size_t)(((int)x0f * RESG + yi) * RESG + zi) * 12;
    const float* gp1 = gp0 + RESG * RESG * 12;
    float4 a0 = *(const float4*)gp0;
    float4 a1 = *(const float4*)(gp0 + 4);
    float4 a2 = *(const float4*)(gp0 + 8);
    float4 b0 = *(const float4*)gp1;
    float4 b1 = *(const float4*)(gp1 + 4);
    float4 b2 = *(const float4*)(gp1 + 8);
    g[0] = a0.x;  g[1] = a0.y;  g[2] = a0.z;  g[3] = a0.w;
    g[4] = a1.x;  g[5] = a1.y;  g[6] = a1.z;  g[7] = a1.w;
    g[8] = a2.x;  g[9] = a2.y;  g[10] = a2.z; g[11] = a2.w;
    g[12] = b0.x; g[13] = b0.y; g[14] = b0.z; g[15] = b0.w;
    g[16] = b1.x; g[17] = b1.y; g[18] = b1.z; g[19] = b1.w;
    g[20] = b2.x; g[21] = b2.y; g[22] = b2.z; g[23] = b2.w;
}

// ---- gather stage B: weight+reduce over the point's 4 threads, store rf ----
__device__ __forceinline__ void gatherB(uint32_t* __restrict__ smu, int rfbase,
                                        int tid, bool valid, const float g[24],
                                        float w0, float w1, float4 xa, float xb) {
    float gv[12];
#pragma unroll
    for (int c = 0; c < 12; c++) gv[c] = fmaf(g[c], w0, g[12 + c] * w1);
#pragma unroll
    for (int c = 0; c < 12; c++) {
        gv[c] += __shfl_xor_sync(0xffffffffu, gv[c], 1);
        gv[c] += __shfl_xor_sync(0xffffffffu, gv[c], 2);
    }
    if (!valid) return;
    const int p = tid >> 2, s2 = tid & 3;
    __half* hsm = (__half*)smu;
    const int par = p & 1;
#define STH(kk, vv) do { int j_ = (kk) >> 1; \
        hsm[(rfbase + p * RRF + physu(j_, par)) * 2 + ((kk) & 1)] = __float2half_rn(vv); } while (0)
    if (s2 == 0) {
#pragma unroll
        for (int c = 0; c < 12; c++) STH(c, gv[c]);
        STH(39, xa.w);
        STH(40, xb);
    } else {
        int d = s2 - 1;
        float vv = xb;
        STH(12 + d, vv);
        float f = 1.f;
#pragma unroll
        for (int m = 0; m < 4; m++) {
            STH(15 + 6 * m + d, __sinf(vv * f));
            STH(15 + 6 * m + 3 + d, __cosf(vv * f));
            f *= 2.f;
        }
    }
#undef STH
}

__global__ void __launch_bounds__(THREADS, 1) fastsurf_h128(
    const float* __restrict__ x, const float* __restrict__ grid,
    const float* __restrict__ dW1, const float* __restrict__ db1,
    const float* __restrict__ dW2, const float* __restrict__ db2,
    const float* __restrict__ dW3, const float* __restrict__ db3,
    const float* __restrict__ rW1, const float* __restrict__ rb1,
    const float* __restrict__ rW2, const float* __restrict__ rb2,
    const float* __restrict__ rW3, const float* __restrict__ rb3,
    float* __restrict__ out) {
    extern __shared__ uint32_t smu[];
    float* smf = (float*)smu;
    const int tid = threadIdx.x;

    // ---- one-time staging ----
    for (int i = tid; i < 8192; i += THREADS) {
        int n = i >> 6, j = i & 63;
        int off = n * RW2 + physu(j, n & 1);
        smu[U_DW2T + off] = packh2(dW2[(2 * j) * 128 + n], dW2[(2 * j + 1) * 128 + n]);
        smu[U_RW2T + off] = packh2(rW2[(2 * j) * 128 + n], rW2[(2 * j + 1) * 128 + n]);
    }
    for (int i = tid; i < 4096; i += THREADS) {
        int n = i >> 5, j = i & 31;
        int k0 = 2 * j, k1 = 2 * j + 1;
        float lo = (k0 < 41) ? rW1[k0 * 128 + n] : 0.f;
        float hi = (k1 < 41) ? rW1[k1 * 128 + n] : 0.f;
        smu[U_RW1T + n * RRF + physu(j, n & 1)] = packh2(lo, hi);
    }
    for (int i = tid; i < 8192; i += THREADS) smu[U_RF0 + i] = 0u;  // both rf bufs
    if (tid < 128) {
        smf[F_DB1 + tid] = db1[tid];
        smf[F_DB2 + tid] = db2[tid];
        smf[F_RB1 + tid] = rb1[tid];
        smf[F_RB2 + tid] = rb2[tid];
        smf[F_DW3 + tid] = dW3[tid];
        smf[F_RW3 + 0 * 128 + tid] = rW3[tid * 3 + 0];
        smf[F_RW3 + 1 * 128 + tid] = rW3[tid * 3 + 1];
        smf[F_RW3 + 2 * 128 + tid] = rW3[tid * 3 + 2];
    }
    if (tid == 0) smf[F_DB3] = db3[0];
    if (tid < 3) smf[F_RB3 + tid] = rb3[tid];
    __syncthreads();

    const int lane = tid & 31, warp = tid >> 5;
    const int chain = warp >> 3;
    const int cw = warp & 7;
    const int mi = cw & 1, ni = cw >> 1;
    const int m0 = mi * 64, n0 = ni * 32;
    const int r = lane >> 2, q = lane & 3;
    const int rp = r & 1;
    const int tloc = tid & 255;
    const int pp = tid >> 2, s2 = tid & 3;

    // ---- prologue: featurize tile0 into rf0 ----
    {
        int t0 = blockIdx.x;
        const float* xq = x + (size_t)(t0 * TILE + pp) * 8;
        float4 xa = *(const float4*)xq;
        float xb = xq[4 + s2];
        float g[24], w0, w1;
        gatherA(grid, xa, tid, g, w0, w1);
        gatherB(smu, U_RF0, tid, true, g, w0, w1, xa, xb);
    }
    __syncthreads();
    int cur = 0;

    if (chain == 0) {
        // ======== DENSITY (warps 0-7) ========
        uint32_t wbd[4][2];
#pragma unroll
        for (int f = 0; f < 4; f++) {
            int n = n0 + f * 8 + r;
            wbd[f][0] = packh2(dW1[(2 * q) * 128 + n], dW1[(2 * q + 1) * 128 + n]);
            float lo = (2 * q + 8 < 12) ? dW1[(2 * q + 8) * 128 + n] : 0.f;
            float hi = (2 * q + 9 < 12) ? dW1[(2 * q + 9) * 128 + n] : 0.f;
            wbd[f][1] = packh2(lo, hi);
        }

        for (int tile = blockIdx.x; tile < NTILES; tile += gridDim.x) {
            const int base = tile * TILE;
            const int nxt = tile + gridDim.x;
            const bool vn = nxt < NTILES;
            const int nbase = vn ? nxt * TILE : 0;
            const float* xq = x + (size_t)(nbase + pp) * 8;
            float4 xa = *(const float4*)xq;      // x prefetch in flight
            float xb = xq[4 + s2];

            const int rfb = cur ? U_RF1 : U_RF0;
            float c[4][4][4];
#pragma unroll
            for (int mb = 0; mb < 4; mb++)
#pragma unroll
                for (int f = 0; f < 4; f++)
                    c[mb][f][0] = c[mb][f][1] = c[mb][f][2] = c[mb][f][3] = 0.f;

            // ---- L1: rf(K16) x dW1 ----
#pragma unroll
            for (int mb = 0; mb < 4; mb++) {
                int ab = rfb + (m0 + mb * 16 + r) * RRF + (rp << 4) + 4 * q;
                uint2 lo = *(const uint2*)(smu + ab);
                uint2 hi = *(const uint2*)(smu + ab + 8 * RRF);
#pragma unroll
                for (int f = 0; f < 4; f++)
                    mma16(c[mb][f], lo.x, hi.x, lo.y, hi.y, wbd[f][0], wbd[f][1]);
            }
#pragma unroll
            for (int mb = 0; mb < 4; mb++) {
                uint32_t p0[4], p1[4];
#pragma unroll
                for (int f = 0; f < 4; f++) {
                    int lc = n0 + f * 8 + 2 * q;
                    float2 b = *(const float2*)(smf + F_DB1 + lc);
                    p0[f] = packh2(fmaxf(c[mb][f][0] + b.x, 0.f),
                                   fmaxf(c[mb][f][1] + b.y, 0.f));
                    p1[f] = packh2(fmaxf(c[mb][f][2] + b.x, 0.f),
                                   fmaxf(c[mb][f][3] + b.y, 0.f));
                }
                int hb = U_HD + (m0 + mb * 16 + r) * RW2 + ((ni ^ rp) << 4) + 4 * q;
                *(uint4*)(smu + hb) = make_uint4(p0[0], p0[1], p0[2], p0[3]);
                *(uint4*)(smu + hb + 8 * RW2) = make_uint4(p1[0], p1[1], p1[2], p1[3]);
            }
            // grid loads for next tile go in flight across the L2 GEMM
            float g[24], w0, w1;
            gatherA(grid, xa, tid, g, w0, w1);
            BARC(1);

            // ---- L2: HD(K128) x dW2 ----
#pragma unroll
            for (int mb = 0; mb < 4; mb++)
#pragma unroll
                for (int f = 0; f < 4; f++)
                    c[mb][f][0] = c[mb][f][1] = c[mb][f][2] = c[mb][f][3] = 0.f;
#pragma unroll
            for (int gg = 0; gg < 4; gg++) {
                uint4 bv[4];
#pragma unroll
                for (int f = 0; f < 4; f++)
                    bv[f] = *(const uint4*)(smu + U_DW2T + (n0 + f * 8 + r) * RW2 +
                                            ((gg ^ rp) << 4) + 4 * q);
#pragma unroll
                for (int mb = 0; mb < 4; mb++) {
                    int ab = U_HD + (m0 + mb * 16 + r) * RW2 + ((gg ^ rp) << 4) + 4 * q;
                    uint4 aL = *(const uint4*)(smu + ab);
                    uint4 aH = *(const uint4*)(smu + ab + 8 * RW2);
#pragma unroll
                    for (int f = 0; f < 4; f++) {
                        mma16(c[mb][f], aL.x, aH.x, aL.y, aH.y, bv[f].x, bv[f].y);
                        mma16(c[mb][f], aL.z, aH.z, aL.w, aH.w, bv[f].z, bv[f].w);
                    }
                }
            }
            // fused sdf head
            float ps[4][2];
#pragma unroll
            for (int mb = 0; mb < 4; mb++) ps[mb][0] = ps[mb][1] = 0.f;
#pragma unroll
            for (int f = 0; f < 4; f++) {
                int lc = n0 + f * 8 + 2 * q;
                float2 b2 = *(const float2*)(smf + F_DB2 + lc);
                float2 w3 = *(const float2*)(smf + F_DW3 + lc);
#pragma unroll
                for (int mb = 0; mb < 4; mb++) {
                    ps[mb][0] = fmaf(fmaxf(c[mb][f][0] + b2.x, 0.f), w3.x,
                                fmaf(fmaxf(c[mb][f][1] + b2.y, 0.f), w3.y, ps[mb][0]));
                    ps[mb][1] = fmaf(fmaxf(c[mb][f][2] + b2.x, 0.f), w3.x,
                                fmaf(fmaxf(c[mb][f][3] + b2.y, 0.f), w3.y, ps[mb][1]));
                }
            }
#pragma unroll
            for (int mb = 0; mb < 4; mb++)
#pragma unroll
                for (int hh = 0; hh < 2; hh++) {
                    ps[mb][hh] += __shfl_xor_sync(0xffffffffu, ps[mb][hh], 1);
                    ps[mb][hh] += __shfl_xor_sync(0xffffffffu, ps[mb][hh], 2);
                }
            if (q == 0) {
#pragma unroll
                for (int mb = 0; mb < 4; mb++) {
                    smf[F_PD + ni * 128 + m0 + mb * 16 + r]     = ps[mb][0];
                    smf[F_PD + ni * 128 + m0 + mb * 16 + r + 8] = ps[mb][1];
                }
            }
            BARC(1);
            if (tloc < 128)
                out[(size_t)(base + tloc) * 4 + 3] =
                    smf[F_PD + tloc] + smf[F_PD + 128 + tloc] +
                    smf[F_PD + 256 + tloc] + smf[F_PD + 384 + tloc] + smf[F_DB3];
            gatherB(smu, cur ? U_RF0 : U_RF1, tid, vn, g, w0, w1, xa, xb);
            __syncthreads();
            cur ^= 1;
        }
    } else {
        // ======== RGB (warps 8-15) ========
        for (int tile = blockIdx.x; tile < NTILES; tile += gridDim.x) {
            const int base = tile * TILE;
            const int nxt = tile + gridDim.x;
            const bool vn = nxt < NTILES;
            const int nbase = vn ? nxt * TILE : 0;
            const float* xq = x + (size_t)(nbase + pp) * 8;
            float4 xa = *(const float4*)xq;
            float xb = xq[4 + s2];

            const int rfb = cur ? U_RF1 : U_RF0;
            float c[4][4][4];
#pragma unroll
            for (int mb = 0; mb < 4; mb++)
#pragma unroll
                for (int f = 0; f < 4; f++)
                    c[mb][f][0] = c[mb][f][1] = c[mb][f][2] = c[mb][f][3] = 0.f;

            // ---- L1: rf(K48 of 64) x rW1 (weights from smem) ----
#pragma unroll
            for (int gg = 0; gg < 2; gg++) {
                uint4 bv[4];
#pragma unroll
                for (int f = 0; f < 4; f++)
                    bv[f] = *(const uint4*)(smu + U_RW1T + (n0 + f * 8 + r) * RRF +
                                            ((gg ^ rp) << 4) + 4 * q);
#pragma unroll
                for (int mb = 0; mb < 4; mb++) {
                    int ab = rfb + (m0 + mb * 16 + r) * RRF + ((gg ^ rp) << 4) + 4 * q;
                    uint4 aL = *(const uint4*)(smu + ab);
                    uint4 aH = *(const uint4*)(smu + ab + 8 * RRF);
#pragma unroll
                    for (int f = 0; f < 4; f++) {
                        mma16(c[mb][f], aL.x, aH.x, aL.y, aH.y, bv[f].x, bv[f].y);
                        if (gg == 0)
                            mma16(c[mb][f], aL.z, aH.z, aL.w, aH.w, bv[f].z, bv[f].w);
                    }
                }
            }
#pragma unroll
            for (int mb = 0; mb < 4; mb++) {
                uint32_t p0[4], p1[4];
#pragma unroll
                for (int f = 0; f < 4; f++) {
                    int lc = n0 + f * 8 + 2 * q;
                    float2 b = *(const float2*)(smf + F_RB1 + lc);
                    p0[f] = packh2(fmaxf(c[mb][f][0] + b.x, 0.f),
                                   fmaxf(c[mb][f][1] + b.y, 0.f));
                    p1[f] = packh2(fmaxf(c[mb][f][2] + b.x, 0.f),
                                   fmaxf(c[mb][f][3] + b.y, 0.f));
                }
                int hb = U_HR + (m0 + mb * 16 + r) * RW2 + ((ni ^ rp) << 4) + 4 * q;
                *(uint4*)(smu + hb) = make_uint4(p0[0], p0[1], p0[2], p0[3]);
                *(uint4*)(smu + hb + 8 * RW2) = make_uint4(p1[0], p1[1], p1[2], p1[3]);
            }
            float g[24], w0, w1;
            gatherA(grid, xa, tid, g, w0, w1);
            BARC(2);

            // ---- L2: HR(K128) x rW2 ----
#pragma unroll
            for (int mb = 0; mb < 4; mb++)
#pragma unroll
                for (int f = 0; f < 4; f++)
                    c[mb][f][0] = c[mb][f][1] = c[mb][f][2] = c[mb][f][3] = 0.f;
#pragma unroll
            for (int gg = 0; gg < 4; gg++) {
                uint4 bv[4];
#pragma unroll
                for (int f = 0; f < 4; f++)
                    bv[f] = *(const uint4*)(smu + U_RW2T + (n0 + f * 8 + r) * RW2 +
                                            ((gg ^ rp) << 4) + 4 * q);
#pragma unroll
                for (int mb = 0; mb < 4; mb++) {
                    int ab = U_HR + (m0 + mb * 16 + r) * RW2 + ((gg ^ rp) << 4) + 4 * q;
                    uint4 aL = *(const uint4*)(smu + ab);
                    uint4 aH = *(const uint4*)(smu + ab + 8 * RW2);
#pragma unroll
                    for (int f = 0; f < 4; f++) {
                        mma16(c[mb][f], aL.x, aH.x, aL.y, aH.y, bv[f].x, bv[f].y);
                        mma16(c[mb][f], aL.z, aH.z, aL.w, aH.w, bv[f].z, bv[f].w);
                    }
                }
            }
            // fused rgb head
            float pc[3][4][2];
#pragma unroll
            for (int ch = 0; ch < 3; ch++)
#pragma unroll
                for (int mb = 0; mb < 4; mb++)
                    pc[ch][mb][0] = pc[ch][mb][1] = 0.f;
#pragma unroll
            for (int f = 0; f < 4; f++) {
                int lc = n0 + f * 8 + 2 * q;
                float2 b2 = *(const float2*)(smf + F_RB2 + lc);
#pragma unroll
                for (int mb = 0; mb < 4; mb++) {
                    float h0 = fmaxf(c[mb][f][0] + b2.x, 0.f);
                    float h1 = fmaxf(c[mb][f][1] + b2.y, 0.f);
                    float h2 = fmaxf(c[mb][f][2] + b2.x, 0.f);
                    float h3 = fmaxf(c[mb][f][3] + b2.y, 0.f);
#pragma unroll
                    for (int ch = 0; ch < 3; ch++) {
                        float2 w3 = *(const float2*)(smf + F_RW3 + ch * 128 + lc);
                        pc[ch][mb][0] = fmaf(h0, w3.x, fmaf(h1, w3.y, pc[ch][mb][0]));
                        pc[ch][mb][1] = fmaf(h2, w3.x, fmaf(h3, w3.y, pc[ch][mb][1]));
                    }
                }
            }
#pragma unroll
            for (int ch = 0; ch < 3; ch++)
#pragma unroll
                for (int mb = 0; mb < 4; mb++)
#pragma unroll
                    for (int hh = 0; hh < 2; hh++) {
                        pc[ch][mb][hh] += __shfl_xor_sync(0xffffffffu, pc[ch][mb][hh], 1);
                        pc[ch][mb][hh] += __shfl_xor_sync(0xffffffffu, pc[ch][mb][hh], 2);
                    }
            if (q == 0) {
#pragma unroll
                for (int ch = 0; ch < 3; ch++)
#pragma unroll
                    for (int mb = 0; mb < 4; mb++) {
                        smf[F_PR + ch * 512 + ni * 128 + m0 + mb * 16 + r]     = pc[ch][mb][0];
                        smf[F_PR + ch * 512 + ni * 128 + m0 + mb * 16 + r + 8] = pc[ch][mb][1];
                    }
            }
            BARC(2);
            if (tloc < 128) {
#pragma unroll
                for (int ch = 0; ch < 3; ch++)
                    out[(size_t)(base + tloc) * 4 + ch] =
                        smf[F_PR + ch * 512 + tloc] + smf[F_PR + ch * 512 + 128 + tloc] +
                        smf[F_PR + ch * 512 + 256 + tloc] + smf[F_PR + ch * 512 + 384 + tloc] +
                        smf[F_RB3 + ch];
            }
            gatherB(smu, cur ? U_RF0 : U_RF1, tid, vn, g, w0, w1, xa, xb);
            __syncthreads();
            cur ^= 1;
        }
    }
}

extern "C" void kernel_launch(void* const* d_in, const int* in_sizes, int n_in,
                              void* d_out, int out_size) {
    (void)in_sizes; (void)n_in; (void)out_size;
    const float* x    = (const float*)d_in[0];
    const float* grid = (const float*)d_in[1];
    const float* dW1  = (const float*)d_in[2];
    const float* db1  = (const float*)d_in[3];
    const float* dW2  = (const float*)d_in[4];
    const float* db2  = (const float*)d_in[5];
    const float* dW3  = (const float*)d_in[6];
    const float* db3  = (const float*)d_in[7];
    const float* rW1  = (const float*)d_in[8];
    const float* rb1  = (const float*)d_in[9];
    const float* rW2  = (const float*)d_in[10];
    const float* rb2  = (const float*)d_in[11];
    const float* rW3  = (const float*)d_in[12];
    const float* rb3  = (const float*)d_in[13];
    float* out = (float*)d_out;

    int nsm = 148;
    cudaDeviceGetAttribute(&nsm, cudaDevAttrMultiProcessorCount, 0);
    cudaFuncSetAttribute(fastsurf_h128,
                         cudaFuncAttributeMaxDynamicSharedMemorySize, SMEM_BYTES);
    fastsurf_h128<<<nsm, THREADS, SMEM_BYTES>>>(x, grid, dW1, db1, dW2, db2, dW3, db3,
                                                rW1, rb1, rW2, rb2, rW3, rb3, out);
}

// round 17
// speedup vs baseline: 1.0807x; 1.0807x over previous
#include <cuda_runtime.h>
#include <cuda_fp16.h>
#include <math.h>
#include <stdint.h>

#define NPTS   (1 << 20)
#define RESG   160
#define TILE   32
#define NTILES (NPTS / TILE)
#define THREADS 256

#define RW2 64   // u32 per row (K=128 halves)
#define RRF 32   // u32 per row (K=64 halves)

// ---- u32 offsets in shared ----
#define U_DW2T 0                 // 128 x 64
#define U_RW2T 8192
#define U_RW1T 16384             // 128 x 32 (rgb L1 weights)
#define U_HD   20480             // 32 x 64
#define U_HR   22528
#define U_RF0  24576             // 32 x 32
#define U_RF1  25600
#define F_DB1  26624
#define F_DB2  (F_DB1 + 128)
#define F_RB1  (F_DB2 + 128)
#define F_RB2  (F_RB1 + 128)
#define F_DW3  (F_RB2 + 128)
#define F_RW3  (F_DW3 + 128)     // [3][128]
#define F_DB3  (F_RW3 + 384)
#define F_RB3  (F_DB3 + 1)       // 3
#define F_PD   (F_RB3 + 3)       // [2][32]
#define F_PR   (F_PD + 64)       // [3][2][32]
#define SMEM_U32   (F_PR + 192)
#define SMEM_BYTES (SMEM_U32 * 4)

#define BARC(id) asm volatile("bar.sync %0, 128;" :: "r"(id) : "memory")

__device__ __forceinline__ int physu(int j, int par) {
    return (((j >> 4) ^ par) << 4) | ((j & 3) << 2) | ((j >> 2) & 3);
}
__device__ __forceinline__ uint32_t packh2(float lo, float hi) {
    __half2 h = __floats2half2_rn(lo, hi);
    return *(uint32_t*)&h;
}
__device__ __forceinline__ void mma16(float c[4], uint32_t a0, uint32_t a1,
                                      uint32_t a2, uint32_t a3,
                                      uint32_t b0, uint32_t b1) {
    asm volatile(
        "mma.sync.aligned.m16n8k16.row.col.f32.f16.f16.f32 "
        "{%0,%1,%2,%3}, {%4,%5,%6,%7}, {%8,%9}, {%0,%1,%2,%3};"
        : "+f"(c[0]), "+f"(c[1]), "+f"(c[2]), "+f"(c[3])
        : "r"(a0), "r"(a1), "r"(a2), "r"(a3), "r"(b0), "r"(b1));
}

// ---- stage A: compute corner addr, issue grid loads into registers ----
__device__ __forceinline__ void gatherA(const float* __restrict__ x,
                                        const float* __restrict__ grid,
                                        int base, int tid, bool valid,
                                        float g[12], float& wgt) {
    if (!valid) {
        wgt = 0.f;
#pragma unroll
        for (int c = 0; c < 12; c++) g[c] = 0.f;
        return;
    }
    const int p = tid >> 3, corner = tid & 7;
    const float* xp = x + (size_t)(base + p) * 8;
    float px = fminf(fmaxf(xp[0], 0.f), 1.f);
    float py = fminf(fmaxf(xp[1], 0.f), 1.f);
    float pz = fminf(fmaxf(xp[2], 0.f), 1.f);
    float fx = px * 159.f, fy = py * 159.f, fz = pz * 159.f;
    float x0f = fminf(floorf(fx), 158.f);
    float y0f = fminf(floorf(fy), 158.f);
    float z0f = fminf(floorf(fz), 158.f);
    float wx = fx - x0f, wy = fy - y0f, wz = fz - z0f;
    int xi = (int)x0f + ((corner >> 2) & 1);
    int yi = (int)y0f + ((corner >> 1) & 1);
    int zi = (int)z0f + (corner & 1);
    wgt = ((corner & 4) ? wx : 1.f - wx) *
          ((corner & 2) ? wy : 1.f - wy) *
          ((corner & 1) ? wz : 1.f - wz);
    const float* gp = grid + (size_t)((xi * RESG + yi) * RESG + zi) * 12;
    float4 g0 = *(const float4*)gp;
    float4 g1 = *(const float4*)(gp + 4);
    float4 g2 = *(const float4*)(gp + 8);
    g[0] = g0.x; g[1] = g0.y; g[2] = g0.z; g[3] = g0.w;
    g[4] = g1.x; g[5] = g1.y; g[6] = g1.z; g[7] = g1.w;
    g[8] = g2.x; g[9] = g2.y; g[10] = g2.z; g[11] = g2.w;
}

// ---- stage B: weight, shuffle-reduce, store to rf buffer ----
__device__ __forceinline__ void gatherB(uint32_t* __restrict__ smu, int rfbase,
                                        const float* __restrict__ x,
                                        int base, int tid, bool valid,
                                        const float g[12], float wgt) {
    float gv[12];
#pragma unroll
    for (int c = 0; c < 12; c++) gv[c] = g[c] * wgt;
#pragma unroll
    for (int off = 4; off; off >>= 1)
#pragma unroll
        for (int c = 0; c < 12; c++)
            gv[c] += __shfl_down_sync(0xffffffffu, gv[c], off);
    if (!valid) return;
    const int p = tid >> 3, corner = tid & 7;
    const float* xp = x + (size_t)(base + p) * 8;   // L1-hit reload
    __half* hsm = (__half*)smu;
    const int par = p & 1;
#define STH(kk, vv) do { int j_ = (kk) >> 1; \
        hsm[(rfbase + p * RRF + physu(j_, par)) * 2 + ((kk) & 1)] = __float2half_rn(vv); } while (0)
    if (corner == 0) {
#pragma unroll
        for (int c = 0; c < 12; c++) STH(c, gv[c]);
    } else if (corner <= 3) {
        int d = corner - 1;
        float vv = xp[5 + d];
        STH(12 + d, vv);
        float f = 1.f;
#pragma unroll
        for (int m = 0; m < 4; m++) {
            STH(15 + 6 * m + d, __sinf(vv * f));
            STH(15 + 6 * m + 3 + d, __cosf(vv * f));
            f *= 2.f;
        }
    } else if (corner == 4) {
        STH(39, xp[3]);
        STH(40, xp[4]);
    }
#undef STH
}

__global__ void __launch_bounds__(THREADS, 2) fastsurf_2c(
    const float* __restrict__ x, const float* __restrict__ grid,
    const float* __restrict__ dW1, const float* __restrict__ db1,
    const float* __restrict__ dW2, const float* __restrict__ db2,
    const float* __restrict__ dW3, const float* __restrict__ db3,
    const float* __restrict__ rW1, const float* __restrict__ rb1,
    const float* __restrict__ rW2, const float* __restrict__ rb2,
    const float* __restrict__ rW3, const float* __restrict__ rb3,
    float* __restrict__ out) {
    extern __shared__ uint32_t smu[];
    float* smf = (float*)smu;
    const int tid = threadIdx.x;

    // ---- one-time staging ----
    for (int i = tid; i < 8192; i += THREADS) {
        int n = i >> 6, j = i & 63;
        int off = n * RW2 + physu(j, n & 1);
        smu[U_DW2T + off] = packh2(dW2[(2 * j) * 128 + n], dW2[(2 * j + 1) * 128 + n]);
        smu[U_RW2T + off] = packh2(rW2[(2 * j) * 128 + n], rW2[(2 * j + 1) * 128 + n]);
    }
    for (int i = tid; i < 4096; i += THREADS) {
        int n = i >> 5, j = i & 31;
        float lo = (2 * j < 41) ? rW1[(2 * j) * 128 + n] : 0.f;
        float hi = (2 * j + 1 < 41) ? rW1[(2 * j + 1) * 128 + n] : 0.f;
        smu[U_RW1T + n * RRF + physu(j, n & 1)] = packh2(lo, hi);
    }
    for (int i = tid; i < 2048; i += THREADS) smu[U_RF0 + i] = 0u;  // both rf bufs
    if (tid < 128) {
        smf[F_DB1 + tid] = db1[tid];
        smf[F_DB2 + tid] = db2[tid];
        smf[F_RB1 + tid] = rb1[tid];
        smf[F_RB2 + tid] = rb2[tid];
        smf[F_DW3 + tid] = dW3[tid];
        smf[F_RW3 + 0 * 128 + tid] = rW3[tid * 3 + 0];
        smf[F_RW3 + 1 * 128 + tid] = rW3[tid * 3 + 1];
        smf[F_RW3 + 2 * 128 + tid] = rW3[tid * 3 + 2];
    }
    if (tid == 0) smf[F_DB3] = db3[0];
    if (tid < 3) smf[F_RB3 + tid] = rb3[tid];
    __syncthreads();

    const int lane = tid & 31, warp = tid >> 5;
    const int chain = warp >> 2;          // 0 = density (w0-3), 1 = rgb (w4-7)
    const int cw = warp & 3;
    const int mi = cw & 1, ni = cw >> 1;  // m16 block x n64 block
    const int m0 = mi * 16, n0 = ni * 64;
    const int r = lane >> 2, q = lane & 3;
    const int rp = r & 1;
    const int tloc = tid & 127;

    // ---- prologue: featurize tile0 into rf0 ----
    {
        int t0 = blockIdx.x;
        bool v = t0 < NTILES;
        float g[12], wgt;
        gatherA(x, grid, t0 * TILE, tid, v, g, wgt);
        gatherB(smu, U_RF0, x, t0 * TILE, tid, v, g, wgt);
    }
    __syncthreads();
    int cur = 0;

    if (chain == 0) {
        // ======== DENSITY ========
        uint32_t wbd[8][2];
#pragma unroll
        for (int f = 0; f < 8; f++) {
            int n = n0 + f * 8 + r;
            wbd[f][0] = packh2(dW1[(2 * q) * 128 + n], dW1[(2 * q + 1) * 128 + n]);
            float lo = (2 * q + 8 < 12) ? dW1[(2 * q + 8) * 128 + n] : 0.f;
            float hi = (2 * q + 9 < 12) ? dW1[(2 * q + 9) * 128 + n] : 0.f;
            wbd[f][1] = packh2(lo, hi);
        }

        for (int tile = blockIdx.x; tile < NTILES; tile += gridDim.x) {
            const int base = tile * TILE;
            const int nxt = tile + gridDim.x;
            const bool vn = nxt < NTILES;
            float g[12], wgt;

            const int rfb = cur ? U_RF1 : U_RF0;
            float c[8][4];
#pragma unroll
            for (int f = 0; f < 8; f++)
                c[f][0] = c[f][1] = c[f][2] = c[f][3] = 0.f;

            // ---- L1: rf(K16) x dW1 ----
            {
                int ab = rfb + (m0 + r) * RRF + (rp << 4) + 4 * q;
                uint2 lo = *(const uint2*)(smu + ab);
                uint2 hi = *(const uint2*)(smu + ab + 8 * RRF);
#pragma unroll
                for (int f = 0; f < 8; f++)
                    mma16(c[f], lo.x, hi.x, lo.y, hi.y, wbd[f][0], wbd[f][1]);
            }
            {
                uint32_t pk0[8], pk1[8];
#pragma unroll
                for (int f = 0; f < 8; f++) {
                    int lc = n0 + f * 8 + 2 * q;
                    float2 b = *(const float2*)(smf + F_DB1 + lc);
                    pk0[f] = packh2(fmaxf(c[f][0] + b.x, 0.f), fmaxf(c[f][1] + b.y, 0.f));
                    pk1[f] = packh2(fmaxf(c[f][2] + b.x, 0.f), fmaxf(c[f][3] + b.y, 0.f));
                }
                int g0 = ((2 * ni) ^ rp) << 4, g1 = ((2 * ni + 1) ^ rp) << 4;
                int rb0 = U_HD + (m0 + r) * RW2 + 4 * q;
                *(uint4*)(smu + rb0 + g0) = make_uint4(pk0[0], pk0[1], pk0[2], pk0[3]);
                *(uint4*)(smu + rb0 + g1) = make_uint4(pk0[4], pk0[5], pk0[6], pk0[7]);
                *(uint4*)(smu + rb0 + 8 * RW2 + g0) = make_uint4(pk1[0], pk1[1], pk1[2], pk1[3]);
                *(uint4*)(smu + rb0 + 8 * RW2 + g1) = make_uint4(pk1[4], pk1[5], pk1[6], pk1[7]);
            }
            gatherA(x, grid, nxt * TILE, tid, vn, g, wgt);  // loads in flight
            BARC(1);

            // ---- L2: HD(K128) x dW2 ----
#pragma unroll
            for (int f = 0; f < 8; f++)
                c[f][0] = c[f][1] = c[f][2] = c[f][3] = 0.f;
#pragma unroll
            for (int gg = 0; gg < 4; gg++) {
                int ab = U_HD + (m0 + r) * RW2 + ((gg ^ rp) << 4) + 4 * q;
                uint4 aL = *(const uint4*)(smu + ab);
                uint4 aH = *(const uint4*)(smu + ab + 8 * RW2);
#pragma unroll
                for (int fh = 0; fh < 2; fh++) {
                    uint4 bv[4];
#pragma unroll
                    for (int ff = 0; ff < 4; ff++)
                        bv[ff] = *(const uint4*)(smu + U_DW2T +
                                 (n0 + (fh * 4 + ff) * 8 + r) * RW2 +
                                 ((gg ^ rp) << 4) + 4 * q);
#pragma unroll
                    for (int ff = 0; ff < 4; ff++) {
                        int f = fh * 4 + ff;
                        mma16(c[f], aL.x, aH.x, aL.y, aH.y, bv[ff].x, bv[ff].y);
                        mma16(c[f], aL.z, aH.z, aL.w, aH.w, bv[ff].z, bv[ff].w);
                    }
                }
            }
            // fused sdf head
            float ps0 = 0.f, ps1 = 0.f;
#pragma unroll
            for (int f = 0; f < 8; f++) {
                int lc = n0 + f * 8 + 2 * q;
                float2 b2 = *(const float2*)(smf + F_DB2 + lc);
                float2 w3 = *(const float2*)(smf + F_DW3 + lc);
                ps0 = fmaf(fmaxf(c[f][0] + b2.x, 0.f), w3.x,
                      fmaf(fmaxf(c[f][1] + b2.y, 0.f), w3.y, ps0));
                ps1 = fmaf(fmaxf(c[f][2] + b2.x, 0.f), w3.x,
                      fmaf(fmaxf(c[f][3] + b2.y, 0.f), w3.y, ps1));
            }
            ps0 += __shfl_xor_sync(0xffffffffu, ps0, 1);
            ps0 += __shfl_xor_sync(0xffffffffu, ps0, 2);
            ps1 += __shfl_xor_sync(0xffffffffu, ps1, 1);
            ps1 += __shfl_xor_sync(0xffffffffu, ps1, 2);
            if (q == 0) {
                smf[F_PD + ni * 32 + m0 + r]     = ps0;
                smf[F_PD + ni * 32 + m0 + r + 8] = ps1;
            }
            BARC(1);
            if (tloc < 32)
                out[(size_t)(base + tloc) * 4 + 3] =
                    smf[F_PD + tloc] + smf[F_PD + 32 + tloc] + smf[F_DB3];
            gatherB(smu, cur ? U_RF0 : U_RF1, x, nxt * TILE, tid, vn, g, wgt);
            __syncthreads();
            cur ^= 1;
        }
    } else {
        // ======== RGB ========
        for (int tile = blockIdx.x; tile < NTILES; tile += gridDim.x) {
            const int base = tile * TILE;
            const int nxt = tile + gridDim.x;
            const bool vn = nxt < NTILES;
            float g[12], wgt;

            const int rfb = cur ? U_RF1 : U_RF0;
            float c[8][4];
#pragma unroll
            for (int f = 0; f < 8; f++)
                c[f][0] = c[f][1] = c[f][2] = c[f][3] = 0.f;

            // ---- L1: rf(K48 of 64) x rW1 (weights from smem) ----
#pragma unroll
            for (int gg = 0; gg < 2; gg++) {
                int ab = rfb + (m0 + r) * RRF + ((gg ^ rp) << 4) + 4 * q;
                uint4 aL = *(const uint4*)(smu + ab);
                uint4 aH = *(const uint4*)(smu + ab + 8 * RRF);
#pragma unroll
                for (int fh = 0; fh < 2; fh++) {
                    uint4 bv[4];
#pragma unroll
                    for (int ff = 0; ff < 4; ff++)
                        bv[ff] = *(const uint4*)(smu + U_RW1T +
                                 (n0 + (fh * 4 + ff) * 8 + r) * RRF +
                                 ((gg ^ rp) << 4) + 4 * q);
#pragma unroll
                    for (int ff = 0; ff < 4; ff++) {
                        int f = fh * 4 + ff;
                        mma16(c[f], aL.x, aH.x, aL.y, aH.y, bv[ff].x, bv[ff].y);
                        if (gg == 0)
                            mma16(c[f], aL.z, aH.z, aL.w, aH.w, bv[ff].z, bv[ff].w);
                    }
                }
            }
            {
                uint32_t pk0[8], pk1[8];
#pragma unroll
                for (int f = 0; f < 8; f++) {
                    int lc = n0 + f * 8 + 2 * q;
                    float2 b = *(const float2*)(smf + F_RB1 + lc);
                    pk0[f] = packh2(fmaxf(c[f][0] + b.x, 0.f), fmaxf(c[f][1] + b.y, 0.f));
                    pk1[f] = packh2(fmaxf(c[f][2] + b.x, 0.f), fmaxf(c[f][3] + b.y, 0.f));
                }
                int g0 = ((2 * ni) ^ rp) << 4, g1 = ((2 * ni + 1) ^ rp) << 4;
                int rb0 = U_HR + (m0 + r) * RW2 + 4 * q;
                *(uint4*)(smu + rb0 + g0) = make_uint4(pk0[0], pk0[1], pk0[2], pk0[3]);
                *(uint4*)(smu + rb0 + g1) = make_uint4(pk0[4], pk0[5], pk0[6], pk0[7]);
                *(uint4*)(smu + rb0 + 8 * RW2 + g0) = make_uint4(pk1[0], pk1[1], pk1[2], pk1[3]);
                *(uint4*)(smu + rb0 + 8 * RW2 + g1) = make_uint4(pk1[4], pk1[5], pk1[6], pk1[7]);
            }
            gatherA(x, grid, nxt * TILE, tid, vn, g, wgt);
            BARC(2);

            // ---- L2: HR(K128) x rW2 ----
#pragma unroll
            for (int f = 0; f < 8; f++)
                c[f][0] = c[f][1] = c[f][2] = c[f][3] = 0.f;
#pragma unroll
            for (int gg = 0; gg < 4; gg++) {
                int ab = U_HR + (m0 + r) * RW2 + ((gg ^ rp) << 4) + 4 * q;
                uint4 aL = *(const uint4*)(smu + ab);
                uint4 aH = *(const uint4*)(smu + ab + 8 * RW2);
#pragma unroll
                for (int fh = 0; fh < 2; fh++) {
                    uint4 bv[4];
#pragma unroll
                    for (int ff = 0; ff < 4; ff++)
                        bv[ff] = *(const uint4*)(smu + U_RW2T +
                                 (n0 + (fh * 4 + ff) * 8 + r) * RW2 +
                                 ((gg ^ rp) << 4) + 4 * q);
#pragma unroll
                    for (int ff = 0; ff < 4; ff++) {
                        int f = fh * 4 + ff;
                        mma16(c[f], aL.x, aH.x, aL.y, aH.y, bv[ff].x, bv[ff].y);
                        mma16(c[f], aL.z, aH.z, aL.w, aH.w, bv[ff].z, bv[ff].w);
                    }
                }
            }
            // fused rgb head
            float pc[3][2];
#pragma unroll
            for (int ch = 0; ch < 3; ch++) pc[ch][0] = pc[ch][1] = 0.f;
#pragma unroll
            for (int f = 0; f < 8; f++) {
                int lc = n0 + f * 8 + 2 * q;
                float2 b2 = *(const float2*)(smf + F_RB2 + lc);
                float h0 = fmaxf(c[f][0] + b2.x, 0.f);
                float h1 = fmaxf(c[f][1] + b2.y, 0.f);
                float h2 = fmaxf(c[f][2] + b2.x, 0.f);
                float h3 = fmaxf(c[f][3] + b2.y, 0.f);
#pragma unroll
                for (int ch = 0; ch < 3; ch++) {
                    float2 w3 = *(const float2*)(smf + F_RW3 + ch * 128 + lc);
                    pc[ch][0] = fmaf(h0, w3.x, fmaf(h1, w3.y, pc[ch][0]));
                    pc[ch][1] = fmaf(h2, w3.x, fmaf(h3, w3.y, pc[ch][1]));
                }
            }
#pragma unroll
            for (int ch = 0; ch < 3; ch++)
#pragma unroll
                for (int hh = 0; hh < 2; hh++) {
                    pc[ch][hh] += __shfl_xor_sync(0xffffffffu, pc[ch][hh], 1);
                    pc[ch][hh] += __shfl_xor_sync(0xffffffffu, pc[ch][hh], 2);
                }
            if (q == 0) {
#pragma unroll
                for (int ch = 0; ch < 3; ch++) {
                    smf[F_PR + ch * 64 + ni * 32 + m0 + r]     = pc[ch][0];
                    smf[F_PR + ch * 64 + ni * 32 + m0 + r + 8] = pc[ch][1];
                }
            }
            BARC(2);
            if (tloc < 32) {
#pragma unroll
                for (int ch = 0; ch < 3; ch++)
                    out[(size_t)(base + tloc) * 4 + ch] =
                        smf[F_PR + ch * 64 + tloc] + smf[F_PR + ch * 64 + 32 + tloc] +
                        smf[F_RB3 + ch];
            }
            gatherB(smu, cur ? U_RF0 : U_RF1, x, nxt * TILE, tid, vn, g, wgt);
            __syncthreads();
            cur ^= 1;
        }
    }
}

extern "C" void kernel_launch(void* const* d_in, const int* in_sizes, int n_in,
                              void* d_out, int out_size) {
    (void)in_sizes; (void)n_in; (void)out_size;
    const float* x    = (const float*)d_in[0];
    const float* grid = (const float*)d_in[1];
    const float* dW1  = (const float*)d_in[2];
    const float* db1  = (const float*)d_in[3];
    const float* dW2  = (const float*)d_in[4];
    const float* db2  = (const float*)d_in[5];
    const float* dW3  = (const float*)d_in[6];
    const float* db3  = (const float*)d_in[7];
    const float* rW1  = (const float*)d_in[8];
    const float* rb1  = (const float*)d_in[9];
    const float* rW2  = (const float*)d_in[10];
    const float* rb2  = (const float*)d_in[11];
    const float* rW3  = (const float*)d_in[12];
    const float* rb3  = (const float*)d_in[13];
    float* out = (float*)d_out;

    int nsm = 148;
    cudaDeviceGetAttribute(&nsm, cudaDevAttrMultiProcessorCount, 0);
    cudaFuncSetAttribute(fastsurf_2c,
                         cudaFuncAttributeMaxDynamicSharedMemorySize, SMEM_BYTES);
    fastsurf_2c<<<2 * nsm, THREADS, SMEM_BYTES>>>(x, grid, dW1, db1, dW2, db2, dW3, db3,
                                                  rW1, rb1, rW2, rb2, rW3, rb3, out);
}